// round 1
// baseline (speedup 1.0000x reference)
#include <cuda_runtime.h>
#include <math.h>

#define BN 32    // B*C images
#define HH 256
#define WW 256
#define FG_INF 1e6f

// scratch: squared row-distance g^2, one float per pixel (8 MB)
__device__ float g_g2[BN * HH * WW];

// ---------------------------------------------------------------------------
// Pass A: per-row 1D distance to nearest background pixel (exact, expanding).
// One block per (image,row). bg = (x == 0.0f)  [NaN compares false -> fg].
// Replicates the reference's INF-seeded scan for all-foreground rows.
// ---------------------------------------------------------------------------
__global__ void __launch_bounds__(WW) row_pass(const float* __restrict__ x) {
    __shared__ unsigned char bg[WW];
    const int row = blockIdx.x;            // [0, BN*HH)
    const int j   = threadIdx.x;           // column
    const float v = x[row * WW + j];
    const unsigned char isbg = (v == 0.0f) ? 1 : 0;
    bg[j] = isbg;
    __syncthreads();

    float g;
    if (isbg) {
        g = 0.0f;
    } else {
        g = -1.0f;
        for (int r = 1; r < WW; ++r) {
            const int l = j - r;
            const int rr = j + r;
            const bool hit = ((l >= 0) && bg[l]) || ((rr < WW) && bg[rr]);
            if (hit) { g = (float)r; break; }
        }
        if (g < 0.0f) {
            // no background anywhere in this row: reference gives
            // min(INF + (j+1), INF + (W - j))
            g = FG_INF + fminf((float)(j + 1), (float)(WW - j));
        }
    }
    g_g2[row * WW + j] = g * g;
}

// ---------------------------------------------------------------------------
// Pass B: column lower-envelope with exact early termination.
//   D2[i,j] = min_k (i-k)^2 + g2[k,j]
// Expand r outward from i; once r^2 >= best, no farther k can improve
// (g2 >= 0), so the result is exactly min over all k in [0,H).
// Thread j of block (i, n) -> all g2 loads are row-contiguous (coalesced).
// ---------------------------------------------------------------------------
__global__ void __launch_bounds__(WW) col_pass(const float* __restrict__ x,
                                               float* __restrict__ out) {
    const int n = blockIdx.y;              // image
    const int i = blockIdx.x;              // row
    const int j = threadIdx.x;             // column
    const float* g2img = g_g2 + n * (HH * WW);

    float best = g2img[i * WW + j];
    for (int r = 1; r < HH; ++r) {
        const float r2 = (float)(r * r);
        if (r2 >= best) break;
        const int up = i - r;
        const int dn = i + r;
        if (up >= 0) best = fminf(best, r2 + g2img[up * WW + j]);
        if (dn < HH) best = fminf(best, r2 + g2img[dn * WW + j]);
    }

    const int idx = (n * HH + i) * WW + j;
    const float xv = x[idx];
    const float d = sqrtf(best);
    out[idx] = isnan(xv) ? xv : d;
}

extern "C" void kernel_launch(void* const* d_in, const int* in_sizes, int n_in,
                              void* d_out, int out_size) {
    const float* x = (const float*)d_in[0];
    float* out = (float*)d_out;

    row_pass<<<BN * HH, WW>>>(x);
    col_pass<<<dim3(HH, BN), WW>>>(x, out);
}

// round 2
// speedup vs baseline: 1.3589x; 1.3589x over previous
#include <cuda_runtime.h>
#include <math.h>

#define BN 32    // B*C images
#define HH 256
#define WW 256
#define FG_INF 1e6f
#define BIGF   3.0e38f   // out-of-range padding (r2 + BIGF never wins, no overflow)

// scratch: squared row-distance g^2 (sign bit = "input was NaN"), 8 MB
__device__ float g_g2[BN * HH * WW];

// ---------------------------------------------------------------------------
// Pass A: per-row 1D distance to nearest background pixel via bitmask search.
// 4 rows per block (blockDim = 256x4). bg = (x == 0.0f); NaN -> foreground.
// All-foreground row replicates the reference's INF-seeded scans:
//   g = 1e6 + min(j+1, W-j).
// ---------------------------------------------------------------------------
__global__ void __launch_bounds__(1024) row_pass(const float* __restrict__ x) {
    __shared__ unsigned m[4][8];          // bg bitmask words per row
    const int row = blockIdx.x * 4 + threadIdx.y;   // [0, BN*HH)
    const int j   = threadIdx.x;                    // column
    const float v = x[row * WW + j];
    const bool isbg = (v == 0.0f);                  // NaN compares false -> fg

    const unsigned bal = __ballot_sync(0xFFFFFFFFu, isbg);
    const int wj  = j >> 5;
    const int bit = j & 31;
    if (bit == 0) m[threadIdx.y][wj] = bal;
    __syncthreads();

    const unsigned* mw = m[threadIdx.y];

    float g;
    if (isbg) {
        g = 0.0f;
    } else {
        // nearest bg to the right (positions > j)
        int dr = 1 << 30;
        unsigned w = (bit == 31) ? 0u : (mw[wj] & (~0u << (bit + 1)));
        if (w) {
            dr = __ffs(w) - 1 - bit;
        } else {
            #pragma unroll
            for (int k = 1; k < 8; ++k) {
                int kk = wj + k;
                if (kk < 8 && mw[kk]) { dr = 32 * k + __ffs(mw[kk]) - 1 - bit; break; }
            }
        }
        // nearest bg to the left (positions < j)
        int dl = 1 << 30;
        unsigned wl = (bit == 0) ? 0u : (mw[wj] & ((1u << bit) - 1u));
        if (wl) {
            dl = bit - (31 - __clz(wl));
        } else {
            #pragma unroll
            for (int k = 1; k < 8; ++k) {
                int kk = wj - k;
                if (kk >= 0 && mw[kk]) { dl = 32 * k + bit - (31 - __clz(mw[kk])); break; }
            }
        }
        int d = min(dl, dr);
        if (d >= (1 << 30)) {
            g = FG_INF + fminf((float)(j + 1), (float)(WW - j));
        } else {
            g = (float)d;
        }
    }

    float s = g * g;
    if (isnan(v)) s = -s;   // g >= 1 for fg pixels, sign bit carries NaN flag
    g_g2[row * WW + j] = s;
}

// ---------------------------------------------------------------------------
// Pass B: column lower-envelope  D2[i,j] = min_k (i-k)^2 + g2[k,j].
// Each thread handles 4 consecutive rows at one column. Unconditional
// radius-4 window (12 independent coalesced loads), exact early-terminating
// tail loop for the rare best > 25 cases.
// ---------------------------------------------------------------------------
__global__ void __launch_bounds__(WW) col_pass(float* __restrict__ out) {
    const int n  = blockIdx.y;            // image
    const int i0 = blockIdx.x * 4;        // first of 4 rows
    const int j  = threadIdx.x;           // column
    const float* __restrict__ g2 = g_g2 + n * (HH * WW) + j;

    // rows i0-4 .. i0+7 (12 rows), out-of-range padded with BIGF
    float v[12];
    bool nanf[4];
    #pragma unroll
    for (int t = 0; t < 12; ++t) {
        const int r = i0 - 4 + t;
        v[t] = (r >= 0 && r < HH) ? __ldg(g2 + r * WW) : BIGF;
    }
    #pragma unroll
    for (int p = 0; p < 4; ++p) {
        nanf[p] = signbit(v[4 + p]);
        // (center values are >= 1 when NaN-flagged, so fabs below is safe)
    }
    #pragma unroll
    for (int t = 0; t < 12; ++t) v[t] = fabsf(v[t]);

    #pragma unroll
    for (int p = 0; p < 4; ++p) {
        const int i = i0 + p;
        const int c = 4 + p;
        float best = v[c];
        #pragma unroll
        for (int r = 1; r <= 4; ++r) {
            const float r2 = (float)(r * r);
            best = fminf(best, r2 + v[c - r]);
            best = fminf(best, r2 + v[c + r]);
        }
        // exact tail: any k with |i-k| = r >= 5 contributes >= r^2
        if (25.0f < best) {
            for (int r = 5; r < HH; ++r) {
                const float r2 = (float)(r * r);
                if (r2 >= best) break;
                const int up = i - r;
                const int dn = i + r;
                if (up >= 0) best = fminf(best, r2 + fabsf(__ldg(g2 + up * WW)));
                if (dn < HH) best = fminf(best, r2 + fabsf(__ldg(g2 + dn * WW)));
            }
        }
        const float d = sqrtf(best);
        out[(n * HH + i) * WW + j] = nanf[p] ? __int_as_float(0x7FC00000) : d;
    }
}

extern "C" void kernel_launch(void* const* d_in, const int* in_sizes, int n_in,
                              void* d_out, int out_size) {
    const float* x = (const float*)d_in[0];
    float* out = (float*)d_out;

    row_pass<<<BN * HH / 4, dim3(WW, 4)>>>(x);
    col_pass<<<dim3(HH / 4, BN), WW>>>(out);
}